// round 16
// baseline (speedup 1.0000x reference)
#include <cuda_runtime.h>
#include <cuda_bf16.h>
#include <math.h>
#include <stdint.h>

// Problem constants
#define DMODEL 512
#define DFF    2048
#define NHEAD  8
#define DK     64
#define NBLK   4
#define BATCH  2
#define SEQ    2048
#define MROWS  (BATCH*SEQ)   // 4096

// ---------------------------------------------------------------------------
// Scratch (device globals — no allocations allowed)
// ---------------------------------------------------------------------------
__device__ float g_h [MROWS*DMODEL];     // fp32 block output (residual stream)
__device__ float g_at[MROWS*DMODEL];     // attention output fp32
__device__ float g_h1[MROWS*DMODEL];     // post-LN1 fp32 (residual for LN2)
__device__ float g_f2[2*MROWS*DMODEL];   // FFN2 split-K partials (2 halves)

// bf16 hi/lo split weights, transposed to [N,K]; Q,K,V contiguous.
#define WOFF_Q  0
#define WOFF_K  262144
#define WOFF_V  524288
#define WOFF_1  786432
#define WOFF_2  1835008
#define WSTRIDE 2883584
__device__ __align__(16) __nv_bfloat16 g_w_hi[NBLK * WSTRIDE];
__device__ __align__(16) __nv_bfloat16 g_w_lo[NBLK * WSTRIDE];

// bf16 activations. hi/lo pairs feed the stream GEMMs (FFN1/FFN2); the whole
// attention path is plain bf16 (dilution-validated R13/R14).
__device__ __align__(16) __nv_bfloat16 g_hh [MROWS*DMODEL]; // h hi
__device__ __align__(16) __nv_bfloat16 g_hl [MROWS*DMODEL]; // h lo
__device__ __align__(16) __nv_bfloat16 g_q  [MROWS*DMODEL]; // Q (prescaled by 0.125*log2e)
__device__ __align__(16) __nv_bfloat16 g_k  [MROWS*DMODEL];
__device__ __align__(16) __nv_bfloat16 g_v  [MROWS*DMODEL];
__device__ __align__(16) __nv_bfloat16 g_h1h[MROWS*DMODEL];
__device__ __align__(16) __nv_bfloat16 g_h1l[MROWS*DMODEL];
__device__ __align__(16) __nv_bfloat16 g_ffh[MROWS*DFF];
__device__ __align__(16) __nv_bfloat16 g_ffl[MROWS*DFF];

// ---------------------------------------------------------------------------
// PTX helpers (sm_80-era features only: valid on compute_103 virtual arch)
// ---------------------------------------------------------------------------
__device__ __forceinline__ uint32_t smem_to_u32(const void* p) {
    uint32_t a;
    asm("{ .reg .u64 t; cvta.to.shared.u64 t, %1; cvt.u32.u64 %0, t; }"
        : "=r"(a) : "l"(p));
    return a;
}
__device__ __forceinline__ void ldsm_x4(uint32_t* r, uint32_t addr) {
    asm volatile("ldmatrix.sync.aligned.m8n8.x4.shared.b16 {%0,%1,%2,%3}, [%4];"
        : "=r"(r[0]), "=r"(r[1]), "=r"(r[2]), "=r"(r[3]) : "r"(addr));
}
__device__ __forceinline__ void ldsm_x4_t(uint32_t* r, uint32_t addr) {
    asm volatile("ldmatrix.sync.aligned.m8n8.x4.trans.shared.b16 {%0,%1,%2,%3}, [%4];"
        : "=r"(r[0]), "=r"(r[1]), "=r"(r[2]), "=r"(r[3]) : "r"(addr));
}
__device__ __forceinline__ void mma_bf16(float* d, const uint32_t* a,
                                         const uint32_t* b) {
    asm volatile(
        "mma.sync.aligned.m16n8k16.row.col.f32.bf16.bf16.f32 "
        "{%0,%1,%2,%3}, {%4,%5,%6,%7}, {%8,%9}, {%0,%1,%2,%3};"
        : "+f"(d[0]), "+f"(d[1]), "+f"(d[2]), "+f"(d[3])
        : "r"(a[0]), "r"(a[1]), "r"(a[2]), "r"(a[3]), "r"(b[0]), "r"(b[1]));
}
__device__ __forceinline__ float ex2f(float x) {
    float y;
    asm("ex2.approx.f32 %0, %1;" : "=f"(y) : "f"(x));
    return y;
}
#define CP_ASYNC16(dst, src) \
    asm volatile("cp.async.cg.shared.global [%0], [%1], 16;" \
        :: "r"(dst), "l"(src))
#define CP_COMMIT() asm volatile("cp.async.commit_group;" ::: "memory")
#define CP_WAIT(N)  asm volatile("cp.async.wait_group %0;" :: "n"(N) : "memory")

// Pack a float pair into bf16x2 hi + bf16x2 lo (hi/lo split).
__device__ __forceinline__ void split2(float a, float b,
                                       uint32_t& hi, uint32_t& lo) {
    __nv_bfloat162 h = __float22bfloat162_rn(make_float2(a, b));
    float2 hf = __bfloat1622float2(h);
    __nv_bfloat162 l = __float22bfloat162_rn(make_float2(a - hf.x, b - hf.y));
    hi = *(uint32_t*)&h;
    lo = *(uint32_t*)&l;
}
__device__ __forceinline__ uint32_t pack_bf16x2(float a, float b) {
    __nv_bfloat162 h = __float22bfloat162_rn(make_float2(a, b));
    return *(uint32_t*)&h;
}

// ---------------------------------------------------------------------------
// Activation split: fp32 -> bf16 hi + bf16 lo (only used for the layer-0 input)
// ---------------------------------------------------------------------------
__global__ void split_kernel(const float* __restrict__ in,
                             __nv_bfloat16* __restrict__ hi,
                             __nv_bfloat16* __restrict__ lo, int n4) {
    int i = blockIdx.x * 256 + threadIdx.x;
    if (i >= n4) return;
    float4 v = ((const float4*)in)[i];
    uint32_t h01, l01, h23, l23;
    split2(v.x, v.y, h01, l01);
    split2(v.z, v.w, h23, l23);
    ((uint32_t*)hi)[2*i]   = h01;
    ((uint32_t*)hi)[2*i+1] = h23;
    ((uint32_t*)lo)[2*i]   = l01;
    ((uint32_t*)lo)[2*i+1] = l23;
}

// ---------------------------------------------------------------------------
// Fused weight transpose + split for ALL layers in one launch.
// ---------------------------------------------------------------------------
__global__ void wsplit_all(const float* __restrict__ Wq,
                           const float* __restrict__ Wk,
                           const float* __restrict__ Wv,
                           const float* __restrict__ W1,
                           const float* __restrict__ W2,
                           __nv_bfloat16* __restrict__ whi,
                           __nv_bfloat16* __restrict__ wlo) {
    const int bid = blockIdx.x;
    const int layer = bid / 2816;
    const int t = bid % 2816;
    const float* src;
    int K, N, n0, k0;
    size_t doff;
    const size_t wb = (size_t)layer * WSTRIDE;
    if (t < 768) {
        int which = t >> 8;
        int tt = t & 255;
        K = 512; N = 512;
        n0 = (tt & 15) * 32; k0 = (tt >> 4) * 32;
        src = (which == 0 ? Wq : which == 1 ? Wk : Wv) + (size_t)layer * 512 * 512;
        doff = wb + (which == 0 ? WOFF_Q : which == 1 ? WOFF_K : WOFF_V);
    } else if (t < 1792) {
        int tt = t - 768;
        K = 512; N = 2048;
        n0 = (tt & 63) * 32; k0 = (tt >> 6) * 32;
        src = W1 + (size_t)layer * 512 * 2048;
        doff = wb + WOFF_1;
    } else {
        int tt = t - 1792;
        K = 2048; N = 512;
        n0 = (tt & 15) * 32; k0 = (tt >> 4) * 32;
        src = W2 + (size_t)layer * 2048 * 512;
        doff = wb + WOFF_2;
    }

    __shared__ float tbuf[32][33];
    const int tx = threadIdx.x, ty = threadIdx.y;
    #pragma unroll
    for (int r = 0; r < 32; r += 8)
        tbuf[ty + r][tx] = src[(size_t)(k0 + ty + r) * N + n0 + tx];
    __syncthreads();
    #pragma unroll
    for (int r = 0; r < 32; r += 8) {
        float v = tbuf[tx][ty + r];
        __nv_bfloat16 h = __float2bfloat16(v);
        __nv_bfloat16 l = __float2bfloat16(v - __bfloat162float(h));
        size_t o = doff + (size_t)(n0 + ty + r) * K + k0 + tx;
        whi[o] = h; wlo[o] = l;
    }
}

// ---------------------------------------------------------------------------
// HMMA GEMM core: C = A[M,K-range] @ B^T (B stored [N,Ktot]) + bias.
// TERMS=3: D = Ahi*Bhi + Ahi*Blo + Alo*Bhi, 32KB stages (A hi|lo, B hi|lo).
// TERMS=1: D = Ahi*Bhi, compact 16KB stages (A, B) -> 3 CTAs/SM possible.
// MODE 2: ReLU + bf16 hi/lo out. MODE 3: fp32, no bias.
// MODE 4: plain bf16 out (scaled by oscale).
// CTA tile 128x128, BK=32, 256 threads, 3-stage cp.async pipeline.
// ---------------------------------------------------------------------------
#define GEMM_SMEM (3*32768)
#define QKV_SMEM  (3*16384)

template<int TERMS>
__device__ __forceinline__ void stage_load(
    uint32_t sbase,
    const __nv_bfloat16* __restrict__ Ahi, const __nv_bfloat16* __restrict__ Alo,
    const __nv_bfloat16* __restrict__ Bhi, const __nv_bfloat16* __restrict__ Blo,
    int tileM, int tileN, int Ktot, int k0, int tid) {
    constexpr uint32_t BOFF = (TERMS == 3) ? 16384u : 8192u;
    #pragma unroll
    for (int h = 0; h < 2; h++) {
        int idx = tid + h * 256;
        int row = idx >> 2;
        int c   = idx & 3;
        uint32_t sw = (uint32_t)row * 64 + (uint32_t)((c ^ ((row >> 1) & 3)) << 4);
        size_t gA = (size_t)(tileM + row) * Ktot + k0 + c * 8;
        size_t gB = (size_t)(tileN + row) * Ktot + k0 + c * 8;
        CP_ASYNC16(sbase +        sw, Ahi + gA);
        CP_ASYNC16(sbase + BOFF + sw, Bhi + gB);
        if (TERMS == 3) {
            CP_ASYNC16(sbase +  8192 + sw, Alo + gA);
            CP_ASYNC16(sbase + 24576 + sw, Blo + gB);
        }
    }
}

template<int MODE, int TERMS>
__device__ __forceinline__ void gemm_core(
    const __nv_bfloat16* __restrict__ Ahi, const __nv_bfloat16* __restrict__ Alo,
    const __nv_bfloat16* __restrict__ Bhi, const __nv_bfloat16* __restrict__ Blo,
    const float* __restrict__ bias,
    float* __restrict__ C,
    __nv_bfloat16* __restrict__ Chi, __nv_bfloat16* __restrict__ Clo,
    int N, int Ktot, int kBase, int Ksub, int tileM, int tileN,
    float oscale, char* smem) {
    constexpr uint32_t STB  = (TERMS == 3) ? 32768u : 16384u;
    constexpr uint32_t BOFF = (TERMS == 3) ? 16384u : 8192u;
    const uint32_t smem_u = smem_to_u32(smem);
    const int tid  = threadIdx.x;
    const int lane = tid & 31;
    const int wid  = tid >> 5;
    const int warp_m = wid & 3;
    const int warp_n = wid >> 2;

    float acc[2][8][4];
    #pragma unroll
    for (int mt = 0; mt < 2; mt++)
        #pragma unroll
        for (int nt = 0; nt < 8; nt++)
            #pragma unroll
            for (int i = 0; i < 4; i++) acc[mt][nt][i] = 0.f;

    const int a_r = lane & 15;
    const int a_h = lane >> 4;
    const int b_r = (lane & 7) + ((lane >> 4) << 3);
    const int b_h = (lane >> 3) & 1;

    const int nIter = Ksub >> 5;
    stage_load<TERMS>(smem_u, Ahi, Alo, Bhi, Blo, tileM, tileN, Ktot, kBase, tid);
    CP_COMMIT();
    if (nIter > 1) {
        stage_load<TERMS>(smem_u + STB, Ahi, Alo, Bhi, Blo,
                          tileM, tileN, Ktot, kBase + 32, tid);
        CP_COMMIT();
    }

    int buf = 0, buf2 = (nIter > 2) ? 2 : 0;
    for (int it = 0; it < nIter; it++) {
        if (it + 1 < nIter) { CP_WAIT(1); } else { CP_WAIT(0); }
        __syncthreads();
        if (it + 2 < nIter) {
            stage_load<TERMS>(smem_u + buf2 * STB,
                              Ahi, Alo, Bhi, Blo, tileM, tileN, Ktot,
                              kBase + ((it + 2) << 5), tid);
            CP_COMMIT();
            buf2 = (buf2 == 2) ? 0 : buf2 + 1;
        }

        const uint32_t sbase = smem_u + buf * STB;
        buf = (buf == 2) ? 0 : buf + 1;
        #pragma unroll
        for (int kc = 0; kc < 2; kc++) {
            uint32_t ah[2][4], al[2][4];
            #pragma unroll
            for (int mt = 0; mt < 2; mt++) {
                int row = warp_m * 32 + mt * 16 + a_r;
                int c16 = kc * 2 + a_h;
                uint32_t off = (uint32_t)row * 64 +
                               (uint32_t)((c16 ^ ((row >> 1) & 3)) << 4);
                ldsm_x4(ah[mt], sbase + off);
                if (TERMS == 3) ldsm_x4(al[mt], sbase + 8192 + off);
            }
            #pragma unroll
            for (int nt2 = 0; nt2 < 4; nt2++) {
                int row = warp_n * 64 + nt2 * 16 + b_r;
                int c16 = kc * 2 + b_h;
                uint32_t off = (uint32_t)row * 64 +
                               (uint32_t)((c16 ^ ((row >> 1) & 3)) << 4);
                uint32_t bh[4], bl[4];
                ldsm_x4(bh, sbase + BOFF + off);
                if (TERMS == 3) ldsm_x4(bl, sbase + 24576 + off);
                #pragma unroll
                for (int mt = 0; mt < 2; mt++) {
                    #pragma unroll
                    for (int half = 0; half < 2; half++) {
                        int nt = nt2 * 2 + half;
                        mma_bf16(acc[mt][nt], ah[mt], bh + half * 2);
                        if (TERMS == 3) {
                            mma_bf16(acc[mt][nt], ah[mt], bl + half * 2);
                            mma_bf16(acc[mt][nt], al[mt], bh + half * 2);
                        }
                    }
                }
            }
        }
    }

    const int l4 = lane >> 2;
    const int l2 = (lane & 3) * 2;
    #pragma unroll
    for (int mt = 0; mt < 2; mt++) {
        #pragma unroll
        for (int nt = 0; nt < 8; nt++) {
            int row = tileM + warp_m * 32 + mt * 16 + l4;
            int col = tileN + warp_n * 64 + nt * 8 + l2;
            float2 bb = (MODE == 3) ? make_float2(0.f, 0.f)
                                    : *(const float2*)(bias + col);
            float v0 = acc[mt][nt][0] + bb.x;
            float v1 = acc[mt][nt][1] + bb.y;
            float v2 = acc[mt][nt][2] + bb.x;
            float v3 = acc[mt][nt][3] + bb.y;
            if (MODE == 4) {
                v0 *= oscale; v1 *= oscale; v2 *= oscale; v3 *= oscale;
            }
            if (MODE == 2) {
                v0 = fmaxf(v0, 0.f); v1 = fmaxf(v1, 0.f);
                v2 = fmaxf(v2, 0.f); v3 = fmaxf(v3, 0.f);
            }
            if (MODE == 3) {
                *(float2*)(C + (size_t)row * N + col)       = make_float2(v0, v1);
                *(float2*)(C + (size_t)(row + 8) * N + col) = make_float2(v2, v3);
            } else if (MODE == 4) {
                *(uint32_t*)(Chi + (size_t)row * N + col)       = pack_bf16x2(v0, v1);
                *(uint32_t*)(Chi + (size_t)(row + 8) * N + col) = pack_bf16x2(v2, v3);
            } else {
                uint32_t h01, l01, h23, l23;
                split2(v0, v1, h01, l01);
                split2(v2, v3, h23, l23);
                *(uint32_t*)(Chi + (size_t)row * N + col)       = h01;
                *(uint32_t*)(Clo + (size_t)row * N + col)       = l01;
                *(uint32_t*)(Chi + (size_t)(row + 8) * N + col) = h23;
                *(uint32_t*)(Clo + (size_t)(row + 8) * N + col) = l23;
            }
        }
    }
}

template<int MODE>
__global__ void __launch_bounds__(256, 2) gemm_hmma(
    const __nv_bfloat16* __restrict__ Ahi, const __nv_bfloat16* __restrict__ Alo,
    const __nv_bfloat16* __restrict__ Bhi, const __nv_bfloat16* __restrict__ Blo,
    const float* __restrict__ bias,
    float* __restrict__ C,
    __nv_bfloat16* __restrict__ Chi, __nv_bfloat16* __restrict__ Clo,
    int N, int Ktot, int Ksub) {
    extern __shared__ char smem[];
    const int kBase = blockIdx.z * Ksub;
    float* Cz = (MODE == 3) ? C + (size_t)blockIdx.z * MROWS * N : C;
    gemm_core<MODE, 3>(Ahi, Alo, Bhi, Blo, bias, Cz, Chi, Clo,
                       N, Ktot, kBase, Ksub, blockIdx.y * 128, blockIdx.x * 128,
                       1.0f, smem);
}

// Fused Q/K/V projection: one launch, grid (12, 32). blockIdx.x selects the
// target matrix (x>>2: 0=Q,1=K,2=V) and its 128-col tile (x&3).
// PLAIN bf16, compact smem (48KB), 3 CTAs/SM -> 384 CTAs in one wave.
// Q prescaled by 0.125*log2(e) so attention uses ex2 directly.
__global__ void __launch_bounds__(256, 3) gemm_qkv(
    const __nv_bfloat16* __restrict__ Ahi,
    const __nv_bfloat16* __restrict__ whi,
    const float* __restrict__ bq, const float* __restrict__ bk,
    const float* __restrict__ bv,
    __nv_bfloat16* __restrict__ q, __nv_bfloat16* __restrict__ k,
    __nv_bfloat16* __restrict__ v) {
    extern __shared__ char smem[];
    const int which = blockIdx.x >> 2;
    const int nx = blockIdx.x & 3;
    const __nv_bfloat16* Bhi = whi + (size_t)which * 262144;
    const float* bias = (which == 0) ? bq : (which == 1) ? bk : bv;
    __nv_bfloat16* Cq = (which == 0) ? q : (which == 1) ? k : v;
    const float oscale = (which == 0) ? 0.125f * 1.4426950408889634f : 1.0f;
    gemm_core<4, 1>(Ahi, nullptr, Bhi, nullptr, bias, nullptr, Cq, nullptr,
                    DMODEL, DMODEL, 0, DMODEL, blockIdx.y * 128, nx * 128,
                    oscale, smem);
}

// ---------------------------------------------------------------------------
// Flash attention with HMMA, plain bf16 (dilution-validated R13/R14).
// 128-q tiles, 256 threads, KV chunks of 64 keys, double-buffered cp.async.
// No online max; Q prescaled by 0.125*log2e -> bare ex2. Row-sum l via
// ones-mma on the packed P fragments.
// SMEM: stage s at s*16384: K 0 | V 8192.  Q at 32768.  Total 48KB.
// ---------------------------------------------------------------------------
#define ATT_SMEM 49152

__device__ __forceinline__ void att_stage_load(
    uint32_t sbase,
    const __nv_bfloat16* __restrict__ k, const __nv_bfloat16* __restrict__ v,
    size_t hoff, int key0, int tid) {
    #pragma unroll
    for (int t = 0; t < 2; t++) {
        int idx = tid + t * 256;
        int row = idx >> 3, c = idx & 7;
        uint32_t off = (uint32_t)row * 128 + (uint32_t)((c ^ (row & 7)) << 4);
        size_t g = hoff + (size_t)(key0 + row) * DMODEL + c * 8;
        CP_ASYNC16(sbase +        off, k + g);
        CP_ASYNC16(sbase + 8192 + off, v + g);
    }
}

__global__ void __launch_bounds__(256, 2) attn_hmma(
    const __nv_bfloat16* __restrict__ q,
    const __nv_bfloat16* __restrict__ k,
    const __nv_bfloat16* __restrict__ v,
    float* __restrict__ o) {
    extern __shared__ char smem[];
    const uint32_t su = smem_to_u32(smem);
    const int tid = threadIdx.x, lane = tid & 31, wid = tid >> 5;
    const int qt = blockIdx.x, hh = blockIdx.y, b = blockIdx.z;
    const size_t hoff = (size_t)b * SEQ * DMODEL + hh * 64;

    for (int i = tid; i < 1024; i += 256) {
        int row = i >> 3, c = i & 7;
        uint32_t off = (uint32_t)row * 128 + (uint32_t)((c ^ (row & 7)) << 4);
        size_t g = hoff + (size_t)(qt * 128 + row) * DMODEL + c * 8;
        *(uint4*)(smem + 32768 + off) = *(const uint4*)(q + g);
    }

    float O[8][4];
    #pragma unroll
    for (int j = 0; j < 8; j++)
        #pragma unroll
        for (int i = 0; i < 4; i++) O[j][i] = 0.f;
    float accl[4] = {0.f, 0.f, 0.f, 0.f};   // row-sum via ones-mma
    const uint32_t ones2[2] = {0x3F803F80u, 0x3F803F80u};  // bf16 1.0 x2

    __syncthreads();
    att_stage_load(su, k, v, hoff, 0, tid);
    CP_COMMIT();

    const int a_r = lane & 15;
    const int a_h = lane >> 4;
    const int b_r = (lane & 7) + ((lane >> 4) << 3);
    const int b_h = (lane >> 3) & 1;
    const int v_r = (lane & 7) + (((lane >> 3) & 1) << 3);
    const int v_h = lane >> 4;

    const int NCH = SEQ / 64;
    for (int ch = 0; ch < NCH; ch++) {
        if (ch + 1 < NCH) {
            att_stage_load(su + ((ch + 1) & 1) * 16384,
                           k, v, hoff, (ch + 1) * 64, tid);
            CP_COMMIT();
            CP_WAIT(1);
        } else {
            CP_WAIT(0);
        }
        __syncthreads();
        const uint32_t sb = su + (ch & 1) * 16384;

        float s[8][4];
        #pragma unroll
        for (int j = 0; j < 8; j++)
            #pragma unroll
            for (int i = 0; i < 4; i++) s[j][i] = 0.f;

        #pragma unroll
        for (int ks = 0; ks < 4; ks++) {
            uint32_t qf[4];
            {
                int row = wid * 16 + a_r;
                int c16 = ks * 2 + a_h;
                uint32_t off = (uint32_t)row * 128 +
                               (uint32_t)((c16 ^ (row & 7)) << 4);
                ldsm_x4(qf, su + 32768 + off);
            }
            #pragma unroll
            for (int j2 = 0; j2 < 4; j2++) {
                int row = j2 * 16 + b_r;
                int c16 = ks * 2 + b_h;
                uint32_t off = (uint32_t)row * 128 +
                               (uint32_t)((c16 ^ (row & 7)) << 4);
                uint32_t kb[4];
                ldsm_x4(kb, sb + off);
                mma_bf16(s[2*j2],   qf, kb);
                mma_bf16(s[2*j2+1], qf, kb + 2);
            }
        }

        // quirk + softmax numerator: p = 2^s (log2e pre-folded)
        #pragma unroll
        for (int j = 0; j < 8; j++) {
            #pragma unroll
            for (int i = 0; i < 4; i++) {
                float vv = s[j][i];
                if (vv == 0.f) vv = -1e9f;     // reference quirk
                s[j][i] = ex2f(vv);            // 2^(-1e9) underflows to 0
            }
        }

        // O += P V; l += P @ ones
        #pragma unroll
        for (int t = 0; t < 4; t++) {
            uint32_t pa[4];
            pa[0] = pack_bf16x2(s[2*t][0],   s[2*t][1]);
            pa[1] = pack_bf16x2(s[2*t][2],   s[2*t][3]);
            pa[2] = pack_bf16x2(s[2*t+1][0], s[2*t+1][1]);
            pa[3] = pack_bf16x2(s[2*t+1][2], s[2*t+1][3]);
            mma_bf16(accl, pa, ones2);
            #pragma unroll
            for (int n2 = 0; n2 < 4; n2++) {
                int row = t * 16 + v_r;
                int c16 = n2 * 2 + v_h;
                uint32_t off = (uint32_t)row * 128 +
                               (uint32_t)((c16 ^ (row & 7)) << 4);
                uint32_t vb[4];
                ldsm_x4_t(vb, sb + 8192 + off);
                mma_bf16(O[2*n2],   pa, vb);
                mma_bf16(O[2*n2+1], pa, vb + 2);
            }
        }
        __syncthreads();
    }

    float i0 = 1.f / accl[0], i1 = 1.f / accl[2];
    int r0 = qt * 128 + wid * 16 + (lane >> 2);
    int colb = hh * 64 + (lane & 3) * 2;
    #pragma unroll
    for (int j = 0; j < 8; j++) {
        int col = colb + j * 8;
        *(float2*)(o + ((size_t)b * SEQ + r0) * DMODEL + col) =
            make_float2(O[j][0] * i0, O[j][1] * i0);
        *(float2*)(o + ((size_t)b * SEQ + r0 + 8) * DMODEL + col) =
            make_float2(O[j][2] * i1, O[j][3] * i1);
    }
}

// ---------------------------------------------------------------------------
// Fused residual-add + LayerNorm, warp-per-row (no block syncs, no smem).
// 256 threads = 8 warps = 8 rows per CTA; each lane holds 16 columns
// (4 x float4 at stride 128). Emits fp32 + bf16 hi/lo.
// ---------------------------------------------------------------------------
__device__ __forceinline__ void ln_row(float x[16], int row, int lane,
                                       const float* __restrict__ g,
                                       const float* __restrict__ beta,
                                       float* __restrict__ out,
                                       __nv_bfloat16* __restrict__ ohi,
                                       __nv_bfloat16* __restrict__ olo) {
    float s = 0.f, s2 = 0.f;
    #pragma unroll
    for (int i = 0; i < 16; i++) { s += x[i]; s2 += x[i] * x[i]; }
    #pragma unroll
    for (int off = 16; off; off >>= 1) {
        s  += __shfl_xor_sync(0xffffffffu, s,  off);
        s2 += __shfl_xor_sync(0xffffffffu, s2, off);
    }
    float mean = s  * (1.f / (float)DMODEL);
    float var  = s2 * (1.f / (float)DMODEL) - mean * mean;
    float rstd = rsqrtf(var + 1e-5f);

    #pragma unroll
    for (int j = 0; j < 4; j++) {
        int col = lane * 4 + j * 128;
        float4 gg = *(const float4*)(g + col);
        float4 bb = *(const float4*)(beta + col);
        float y0 = (x[4*j+0] - mean) * rstd * gg.x + bb.x;
        float y1 = (x[4*j+1] - mean) * rstd * gg.y + bb.y;
        float y2 = (x[4*j+2] - mean) * rstd * gg.z + bb.z;
        float y3 = (x[4*j+3] - mean) * rstd * gg.w + bb.w;
        *(float4*)(out + (size_t)row * DMODEL + col) =
            make_float4(y0, y1, y2, y3);
        uint32_t h01, l01, h23, l23;
        split2(y0, y1, h01, l01);
        split2(y2, y3, h23, l23);
        uint2* ph = (uint2*)(ohi + (size_t)row * DMODEL + col);
        uint2* pl = (uint2*)(olo + (size_t)row * DMODEL + col);
        *ph = make_uint2(h01, h23);
        *pl = make_uint2(l01, l23);
    }
}

__global__ void __launch_bounds__(256) add_ln_kernel(
    const float* __restrict__ a, const float* __restrict__ r,
    const float* __restrict__ g, const float* __restrict__ beta,
    float* __restrict__ out,
    __nv_bfloat16* __restrict__ ohi, __nv_bfloat16* __restrict__ olo) {
    const int row = blockIdx.x * 8 + (threadIdx.x >> 5);
    const int lane = threadIdx.x & 31;
    float x[16];
    #pragma unroll
    for (int j = 0; j < 4; j++) {
        int col = lane * 4 + j * 128;
        float4 va = *(const float4*)(a + (size_t)row * DMODEL + col);
        float4 vr = *(const float4*)(r + (size_t)row * DMODEL + col);
        x[4*j+0] = va.x + vr.x;
        x[4*j+1] = va.y + vr.y;
        x[4*j+2] = va.z + vr.z;
        x[4*j+3] = va.w + vr.w;
    }
    ln_row(x, row, lane, g, beta, out, ohi, olo);
}

__global__ void __launch_bounds__(256) add_ln3_kernel(
    const float* __restrict__ a0, const float* __restrict__ a1,
    const float* __restrict__ b2, const float* __restrict__ r,
    const float* __restrict__ g, const float* __restrict__ beta,
    float* __restrict__ out,
    __nv_bfloat16* __restrict__ ohi, __nv_bfloat16* __restrict__ olo) {
    const int row = blockIdx.x * 8 + (threadIdx.x >> 5);
    const int lane = threadIdx.x & 31;
    float x[16];
    #pragma unroll
    for (int j = 0; j < 4; j++) {
        int col = lane * 4 + j * 128;
        float4 v0 = *(const float4*)(a0 + (size_t)row * DMODEL + col);
        float4 v1 = *(const float4*)(a1 + (size_t)row * DMODEL + col);
        float4 vb = *(const float4*)(b2 + col);
        float4 vr = *(const float4*)(r + (size_t)row * DMODEL + col);
        x[4*j+0] = v0.x + v1.x + vb.x + vr.x;
        x[4*j+1] = v0.y + v1.y + vb.y + vr.y;
        x[4*j+2] = v0.z + v1.z + vb.z + vr.z;
        x[4*j+3] = v0.w + v1.w + vb.w + vr.w;
    }
    ln_row(x, row, lane, g, beta, out, ohi, olo);
}

// ---------------------------------------------------------------------------
// Launch
// ---------------------------------------------------------------------------
extern "C" void kernel_launch(void* const* d_in, const int* in_sizes, int n_in,
                              void* d_out, int out_size) {
    const float* x   = (const float*)d_in[0];
    const float* Wq  = (const float*)d_in[1];
    const float* bq  = (const float*)d_in[2];
    const float* Wk  = (const float*)d_in[3];
    const float* bk  = (const float*)d_in[4];
    const float* Wv  = (const float*)d_in[5];
    const float* bv  = (const float*)d_in[6];
    const float* W1  = (const float*)d_in[7];
    const float* b1  = (const float*)d_in[8];
    const float* W2  = (const float*)d_in[9];
    const float* b2  = (const float*)d_in[10];
    const float* g1  = (const float*)d_in[11];
    const float* be1 = (const float*)d_in[12];
    const float* g2  = (const float*)d_in[13];
    const float* be2 = (const float*)d_in[14];
    float* out = (float*)d_out;

    float *h_, *at_, *h1_, *f2_;
    cudaGetSymbolAddress((void**)&h_,  g_h);
    cudaGetSymbolAddress((void**)&at_, g_at);
    cudaGetSymbolAddress((void**)&h1_, g_h1);
    cudaGetSymbolAddress((void**)&f2_, g_f2);
    __nv_bfloat16 *whi, *wlo;
    cudaGetSymbolAddress((void**)&whi, g_w_hi);
    cudaGetSymbolAddress((void**)&wlo, g_w_lo);
    __nv_bfloat16 *hh, *hl, *q_, *k_, *v_, *h1h, *h1l, *ffh, *ffl;
    cudaGetSymbolAddress((void**)&hh,  g_hh);
    cudaGetSymbolAddress((void**)&hl,  g_hl);
    cudaGetSymbolAddress((void**)&q_,  g_q);
    cudaGetSymbolAddress((void**)&k_,  g_k);
    cudaGetSymbolAddress((void**)&v_,  g_v);
    cudaGetSymbolAddress((void**)&h1h, g_h1h);
    cudaGetSymbolAddress((void**)&h1l, g_h1l);
    cudaGetSymbolAddress((void**)&ffh, g_ffh);
    cudaGetSymbolAddress((void**)&ffl, g_ffl);

    cudaFuncSetAttribute(gemm_hmma<2>,
                         cudaFuncAttributeMaxDynamicSharedMemorySize, GEMM_SMEM);
    cudaFuncSetAttribute(gemm_hmma<3>,
                         cudaFuncAttributeMaxDynamicSharedMemorySize, GEMM_SMEM);
    cudaFuncSetAttribute(gemm_qkv,
                         cudaFuncAttributeMaxDynamicSharedMemorySize, QKV_SMEM);
    cudaFuncSetAttribute(attn_hmma,
                         cudaFuncAttributeMaxDynamicSharedMemorySize, ATT_SMEM);

    const int M = MROWS;
    dim3 thr256(256);

    // Pre-split + transpose all weights (single launch).
    wsplit_all<<<NBLK * 2816, dim3(32, 8)>>>(Wq, Wk, Wv, W1, W2, whi, wlo);

    dim3 g_qkv(12, M/128);               // fused QKV: 384 CTAs (one wave @3/SM)
    dim3 g_ff1(DFF/128,    M/128);       // (16, 32) = 512 CTAs
    dim3 g_ff2(DMODEL/128, M/128, 2);    // split-K=2: 256 CTAs
    dim3 g_att(SEQ/128, NHEAD, BATCH);   // (16, 8, 2) = 256 CTAs
    const int g_ln = M / 8;              // warp-per-row LN: 512 CTAs

    // Layer-0 input split.
    split_kernel<<<(M*DMODEL/4 + 255)/256, thr256>>>(x, hh, hl, M*DMODEL/4);

    for (int l = 0; l < NBLK; l++) {
        const float* hin = (l == 0) ? x : h_;
        size_t wb = (size_t)l * WSTRIDE;

        gemm_qkv<<<g_qkv, thr256, QKV_SMEM>>>(
            hh, whi + wb,
            bq + (size_t)l*DMODEL, bk + (size_t)l*DMODEL, bv + (size_t)l*DMODEL,
            q_, k_, v_);

        attn_hmma<<<g_att, thr256, ATT_SMEM>>>(q_, k_, v_, at_);

        add_ln_kernel<<<g_ln, thr256>>>(at_, hin, g1 + (size_t)l*DMODEL,
                                        be1 + (size_t)l*DMODEL, h1_, h1h, h1l);

        gemm_hmma<2><<<g_ff1, thr256, GEMM_SMEM>>>(
            h1h, h1l, whi + wb + WOFF_1, wlo + wb + WOFF_1,
            b1 + (size_t)l*DFF, nullptr, ffh, ffl, DFF, DMODEL, DMODEL);

        gemm_hmma<3><<<g_ff2, thr256, GEMM_SMEM>>>(
            ffh, ffl, whi + wb + WOFF_2, wlo + wb + WOFF_2,
            nullptr, f2_, nullptr, nullptr, DMODEL, DFF, DFF/2);

        float* hout = (l == NBLK - 1) ? out : h_;
        add_ln3_kernel<<<g_ln, thr256>>>(f2_, f2_ + (size_t)M*DMODEL,
                                         b2 + (size_t)l*DMODEL, h1_,
                                         g2 + (size_t)l*DMODEL,
                                         be2 + (size_t)l*DMODEL, hout, hh, hl);
    }
}

// round 17
// speedup vs baseline: 1.0439x; 1.0439x over previous
#include <cuda_runtime.h>
#include <cuda_bf16.h>
#include <math.h>
#include <stdint.h>

// Problem constants
#define DMODEL 512
#define DFF    2048
#define NHEAD  8
#define DK     64
#define NBLK   4
#define BATCH  2
#define SEQ    2048
#define MROWS  (BATCH*SEQ)   // 4096

// ---------------------------------------------------------------------------
// Scratch (device globals — no allocations allowed)
// ---------------------------------------------------------------------------
__device__ float g_h [MROWS*DMODEL];     // fp32 block output (residual stream)
__device__ float g_at[MROWS*DMODEL];     // attention output fp32
__device__ float g_h1[MROWS*DMODEL];     // post-LN1 fp32 (residual for LN2)
__device__ float g_f2[2*MROWS*DMODEL];   // FFN2 split-K partials (2 halves)

// bf16 hi/lo split weights, transposed to [N,K]; Q,K,V contiguous.
#define WOFF_Q  0
#define WOFF_K  262144
#define WOFF_V  524288
#define WOFF_1  786432
#define WOFF_2  1835008
#define WSTRIDE 2883584
__device__ __align__(16) __nv_bfloat16 g_w_hi[NBLK * WSTRIDE];
__device__ __align__(16) __nv_bfloat16 g_w_lo[NBLK * WSTRIDE];

// bf16 activations. hi/lo pairs feed the stream GEMMs (FFN1/FFN2); the whole
// attention path is plain bf16 (dilution-validated R13/R14).
__device__ __align__(16) __nv_bfloat16 g_hh [MROWS*DMODEL]; // h hi
__device__ __align__(16) __nv_bfloat16 g_hl [MROWS*DMODEL]; // h lo
__device__ __align__(16) __nv_bfloat16 g_q  [MROWS*DMODEL]; // Q (prescaled by 0.125*log2e)
__device__ __align__(16) __nv_bfloat16 g_k  [MROWS*DMODEL];
__device__ __align__(16) __nv_bfloat16 g_v  [MROWS*DMODEL];
__device__ __align__(16) __nv_bfloat16 g_h1h[MROWS*DMODEL];
__device__ __align__(16) __nv_bfloat16 g_h1l[MROWS*DMODEL];
__device__ __align__(16) __nv_bfloat16 g_ffh[MROWS*DFF];
__device__ __align__(16) __nv_bfloat16 g_ffl[MROWS*DFF];

// ---------------------------------------------------------------------------
// PTX helpers (sm_80-era features only: valid on compute_103 virtual arch)
// ---------------------------------------------------------------------------
__device__ __forceinline__ uint32_t smem_to_u32(const void* p) {
    uint32_t a;
    asm("{ .reg .u64 t; cvta.to.shared.u64 t, %1; cvt.u32.u64 %0, t; }"
        : "=r"(a) : "l"(p));
    return a;
}
__device__ __forceinline__ void ldsm_x4(uint32_t* r, uint32_t addr) {
    asm volatile("ldmatrix.sync.aligned.m8n8.x4.shared.b16 {%0,%1,%2,%3}, [%4];"
        : "=r"(r[0]), "=r"(r[1]), "=r"(r[2]), "=r"(r[3]) : "r"(addr));
}
__device__ __forceinline__ void ldsm_x4_t(uint32_t* r, uint32_t addr) {
    asm volatile("ldmatrix.sync.aligned.m8n8.x4.trans.shared.b16 {%0,%1,%2,%3}, [%4];"
        : "=r"(r[0]), "=r"(r[1]), "=r"(r[2]), "=r"(r[3]) : "r"(addr));
}
__device__ __forceinline__ void mma_bf16(float* d, const uint32_t* a,
                                         const uint32_t* b) {
    asm volatile(
        "mma.sync.aligned.m16n8k16.row.col.f32.bf16.bf16.f32 "
        "{%0,%1,%2,%3}, {%4,%5,%6,%7}, {%8,%9}, {%0,%1,%2,%3};"
        : "+f"(d[0]), "+f"(d[1]), "+f"(d[2]), "+f"(d[3])
        : "r"(a[0]), "r"(a[1]), "r"(a[2]), "r"(a[3]), "r"(b[0]), "r"(b[1]));
}
__device__ __forceinline__ float ex2f(float x) {
    float y;
    asm("ex2.approx.f32 %0, %1;" : "=f"(y) : "f"(x));
    return y;
}
#define CP_ASYNC16(dst, src) \
    asm volatile("cp.async.cg.shared.global [%0], [%1], 16;" \
        :: "r"(dst), "l"(src))
#define CP_COMMIT() asm volatile("cp.async.commit_group;" ::: "memory")
#define CP_WAIT(N)  asm volatile("cp.async.wait_group %0;" :: "n"(N) : "memory")

// Pack a float pair into bf16x2 hi + bf16x2 lo (hi/lo split).
__device__ __forceinline__ void split2(float a, float b,
                                       uint32_t& hi, uint32_t& lo) {
    __nv_bfloat162 h = __float22bfloat162_rn(make_float2(a, b));
    float2 hf = __bfloat1622float2(h);
    __nv_bfloat162 l = __float22bfloat162_rn(make_float2(a - hf.x, b - hf.y));
    hi = *(uint32_t*)&h;
    lo = *(uint32_t*)&l;
}
__device__ __forceinline__ uint32_t pack_bf16x2(float a, float b) {
    __nv_bfloat162 h = __float22bfloat162_rn(make_float2(a, b));
    return *(uint32_t*)&h;
}

// ---------------------------------------------------------------------------
// Activation split: fp32 -> bf16 hi + bf16 lo (only used for the layer-0 input)
// ---------------------------------------------------------------------------
__global__ void split_kernel(const float* __restrict__ in,
                             __nv_bfloat16* __restrict__ hi,
                             __nv_bfloat16* __restrict__ lo, int n4) {
    int i = blockIdx.x * 256 + threadIdx.x;
    if (i >= n4) return;
    float4 v = ((const float4*)in)[i];
    uint32_t h01, l01, h23, l23;
    split2(v.x, v.y, h01, l01);
    split2(v.z, v.w, h23, l23);
    ((uint32_t*)hi)[2*i]   = h01;
    ((uint32_t*)hi)[2*i+1] = h23;
    ((uint32_t*)lo)[2*i]   = l01;
    ((uint32_t*)lo)[2*i+1] = l23;
}

// ---------------------------------------------------------------------------
// Fused weight transpose + split for ALL layers in one launch.
// ---------------------------------------------------------------------------
__global__ void wsplit_all(const float* __restrict__ Wq,
                           const float* __restrict__ Wk,
                           const float* __restrict__ Wv,
                           const float* __restrict__ W1,
                           const float* __restrict__ W2,
                           __nv_bfloat16* __restrict__ whi,
                           __nv_bfloat16* __restrict__ wlo) {
    const int bid = blockIdx.x;
    const int layer = bid / 2816;
    const int t = bid % 2816;
    const float* src;
    int K, N, n0, k0;
    size_t doff;
    const size_t wb = (size_t)layer * WSTRIDE;
    if (t < 768) {
        int which = t >> 8;
        int tt = t & 255;
        K = 512; N = 512;
        n0 = (tt & 15) * 32; k0 = (tt >> 4) * 32;
        src = (which == 0 ? Wq : which == 1 ? Wk : Wv) + (size_t)layer * 512 * 512;
        doff = wb + (which == 0 ? WOFF_Q : which == 1 ? WOFF_K : WOFF_V);
    } else if (t < 1792) {
        int tt = t - 768;
        K = 512; N = 2048;
        n0 = (tt & 63) * 32; k0 = (tt >> 6) * 32;
        src = W1 + (size_t)layer * 512 * 2048;
        doff = wb + WOFF_1;
    } else {
        int tt = t - 1792;
        K = 2048; N = 512;
        n0 = (tt & 15) * 32; k0 = (tt >> 4) * 32;
        src = W2 + (size_t)layer * 2048 * 512;
        doff = wb + WOFF_2;
    }

    __shared__ float tbuf[32][33];
    const int tx = threadIdx.x, ty = threadIdx.y;
    #pragma unroll
    for (int r = 0; r < 32; r += 8)
        tbuf[ty + r][tx] = src[(size_t)(k0 + ty + r) * N + n0 + tx];
    __syncthreads();
    #pragma unroll
    for (int r = 0; r < 32; r += 8) {
        float v = tbuf[tx][ty + r];
        __nv_bfloat16 h = __float2bfloat16(v);
        __nv_bfloat16 l = __float2bfloat16(v - __bfloat162float(h));
        size_t o = doff + (size_t)(n0 + ty + r) * K + k0 + tx;
        whi[o] = h; wlo[o] = l;
    }
}

// ---------------------------------------------------------------------------
// HMMA GEMM core: C = A[M,K-range] @ B^T (B stored [N,Ktot]) + bias.
// TERMS=3: D = Ahi*Bhi + Ahi*Blo + Alo*Bhi, 32KB stages (A hi|lo, B hi|lo).
// TERMS=1: D = Ahi*Bhi, compact 16KB stages (A, B).
// MODE 2: ReLU + bf16 hi/lo out. MODE 3: fp32, no bias.
// MODE 4: plain bf16 out (scaled by oscale).
// CTA tile 128x128, BK=32, 256 threads, 3-stage cp.async pipeline.
// ---------------------------------------------------------------------------
#define GEMM_SMEM (3*32768)
#define QKV_SMEM  (3*16384)

template<int TERMS>
__device__ __forceinline__ void stage_load(
    uint32_t sbase,
    const __nv_bfloat16* __restrict__ Ahi, const __nv_bfloat16* __restrict__ Alo,
    const __nv_bfloat16* __restrict__ Bhi, const __nv_bfloat16* __restrict__ Blo,
    int tileM, int tileN, int Ktot, int k0, int tid) {
    constexpr uint32_t BOFF = (TERMS == 3) ? 16384u : 8192u;
    #pragma unroll
    for (int h = 0; h < 2; h++) {
        int idx = tid + h * 256;
        int row = idx >> 2;
        int c   = idx & 3;
        uint32_t sw = (uint32_t)row * 64 + (uint32_t)((c ^ ((row >> 1) & 3)) << 4);
        size_t gA = (size_t)(tileM + row) * Ktot + k0 + c * 8;
        size_t gB = (size_t)(tileN + row) * Ktot + k0 + c * 8;
        CP_ASYNC16(sbase +        sw, Ahi + gA);
        CP_ASYNC16(sbase + BOFF + sw, Bhi + gB);
        if (TERMS == 3) {
            CP_ASYNC16(sbase +  8192 + sw, Alo + gA);
            CP_ASYNC16(sbase + 24576 + sw, Blo + gB);
        }
    }
}

template<int MODE, int TERMS>
__device__ __forceinline__ void gemm_core(
    const __nv_bfloat16* __restrict__ Ahi, const __nv_bfloat16* __restrict__ Alo,
    const __nv_bfloat16* __restrict__ Bhi, const __nv_bfloat16* __restrict__ Blo,
    const float* __restrict__ bias,
    float* __restrict__ C,
    __nv_bfloat16* __restrict__ Chi, __nv_bfloat16* __restrict__ Clo,
    int N, int Ktot, int kBase, int Ksub, int tileM, int tileN,
    float oscale, char* smem) {
    constexpr uint32_t STB  = (TERMS == 3) ? 32768u : 16384u;
    constexpr uint32_t BOFF = (TERMS == 3) ? 16384u : 8192u;
    const uint32_t smem_u = smem_to_u32(smem);
    const int tid  = threadIdx.x;
    const int lane = tid & 31;
    const int wid  = tid >> 5;
    const int warp_m = wid & 3;
    const int warp_n = wid >> 2;

    float acc[2][8][4];
    #pragma unroll
    for (int mt = 0; mt < 2; mt++)
        #pragma unroll
        for (int nt = 0; nt < 8; nt++)
            #pragma unroll
            for (int i = 0; i < 4; i++) acc[mt][nt][i] = 0.f;

    const int a_r = lane & 15;
    const int a_h = lane >> 4;
    const int b_r = (lane & 7) + ((lane >> 4) << 3);
    const int b_h = (lane >> 3) & 1;

    const int nIter = Ksub >> 5;
    stage_load<TERMS>(smem_u, Ahi, Alo, Bhi, Blo, tileM, tileN, Ktot, kBase, tid);
    CP_COMMIT();
    if (nIter > 1) {
        stage_load<TERMS>(smem_u + STB, Ahi, Alo, Bhi, Blo,
                          tileM, tileN, Ktot, kBase + 32, tid);
        CP_COMMIT();
    }

    int buf = 0, buf2 = (nIter > 2) ? 2 : 0;
    for (int it = 0; it < nIter; it++) {
        if (it + 1 < nIter) { CP_WAIT(1); } else { CP_WAIT(0); }
        __syncthreads();
        if (it + 2 < nIter) {
            stage_load<TERMS>(smem_u + buf2 * STB,
                              Ahi, Alo, Bhi, Blo, tileM, tileN, Ktot,
                              kBase + ((it + 2) << 5), tid);
            CP_COMMIT();
            buf2 = (buf2 == 2) ? 0 : buf2 + 1;
        }

        const uint32_t sbase = smem_u + buf * STB;
        buf = (buf == 2) ? 0 : buf + 1;
        #pragma unroll
        for (int kc = 0; kc < 2; kc++) {
            uint32_t ah[2][4], al[2][4];
            #pragma unroll
            for (int mt = 0; mt < 2; mt++) {
                int row = warp_m * 32 + mt * 16 + a_r;
                int c16 = kc * 2 + a_h;
                uint32_t off = (uint32_t)row * 64 +
                               (uint32_t)((c16 ^ ((row >> 1) & 3)) << 4);
                ldsm_x4(ah[mt], sbase + off);
                if (TERMS == 3) ldsm_x4(al[mt], sbase + 8192 + off);
            }
            #pragma unroll
            for (int nt2 = 0; nt2 < 4; nt2++) {
                int row = warp_n * 64 + nt2 * 16 + b_r;
                int c16 = kc * 2 + b_h;
                uint32_t off = (uint32_t)row * 64 +
                               (uint32_t)((c16 ^ ((row >> 1) & 3)) << 4);
                uint32_t bh[4], bl[4];
                ldsm_x4(bh, sbase + BOFF + off);
                if (TERMS == 3) ldsm_x4(bl, sbase + 24576 + off);
                #pragma unroll
                for (int mt = 0; mt < 2; mt++) {
                    #pragma unroll
                    for (int half = 0; half < 2; half++) {
                        int nt = nt2 * 2 + half;
                        mma_bf16(acc[mt][nt], ah[mt], bh + half * 2);
                        if (TERMS == 3) {
                            mma_bf16(acc[mt][nt], ah[mt], bl + half * 2);
                            mma_bf16(acc[mt][nt], al[mt], bh + half * 2);
                        }
                    }
                }
            }
        }
    }

    const int l4 = lane >> 2;
    const int l2 = (lane & 3) * 2;
    #pragma unroll
    for (int mt = 0; mt < 2; mt++) {
        #pragma unroll
        for (int nt = 0; nt < 8; nt++) {
            int row = tileM + warp_m * 32 + mt * 16 + l4;
            int col = tileN + warp_n * 64 + nt * 8 + l2;
            float2 bb = (MODE == 3) ? make_float2(0.f, 0.f)
                                    : *(const float2*)(bias + col);
            float v0 = acc[mt][nt][0] + bb.x;
            float v1 = acc[mt][nt][1] + bb.y;
            float v2 = acc[mt][nt][2] + bb.x;
            float v3 = acc[mt][nt][3] + bb.y;
            if (MODE == 4) {
                v0 *= oscale; v1 *= oscale; v2 *= oscale; v3 *= oscale;
            }
            if (MODE == 2) {
                v0 = fmaxf(v0, 0.f); v1 = fmaxf(v1, 0.f);
                v2 = fmaxf(v2, 0.f); v3 = fmaxf(v3, 0.f);
            }
            if (MODE == 3) {
                *(float2*)(C + (size_t)row * N + col)       = make_float2(v0, v1);
                *(float2*)(C + (size_t)(row + 8) * N + col) = make_float2(v2, v3);
            } else if (MODE == 4) {
                *(uint32_t*)(Chi + (size_t)row * N + col)       = pack_bf16x2(v0, v1);
                *(uint32_t*)(Chi + (size_t)(row + 8) * N + col) = pack_bf16x2(v2, v3);
            } else {
                uint32_t h01, l01, h23, l23;
                split2(v0, v1, h01, l01);
                split2(v2, v3, h23, l23);
                *(uint32_t*)(Chi + (size_t)row * N + col)       = h01;
                *(uint32_t*)(Clo + (size_t)row * N + col)       = l01;
                *(uint32_t*)(Chi + (size_t)(row + 8) * N + col) = h23;
                *(uint32_t*)(Clo + (size_t)(row + 8) * N + col) = l23;
            }
        }
    }
}

template<int MODE>
__global__ void __launch_bounds__(256, 2) gemm_hmma(
    const __nv_bfloat16* __restrict__ Ahi, const __nv_bfloat16* __restrict__ Alo,
    const __nv_bfloat16* __restrict__ Bhi, const __nv_bfloat16* __restrict__ Blo,
    const float* __restrict__ bias,
    float* __restrict__ C,
    __nv_bfloat16* __restrict__ Chi, __nv_bfloat16* __restrict__ Clo,
    int N, int Ktot, int Ksub) {
    extern __shared__ char smem[];
    const int kBase = blockIdx.z * Ksub;
    float* Cz = (MODE == 3) ? C + (size_t)blockIdx.z * MROWS * N : C;
    gemm_core<MODE, 3>(Ahi, Alo, Bhi, Blo, bias, Cz, Chi, Clo,
                       N, Ktot, kBase, Ksub, blockIdx.y * 128, blockIdx.x * 128,
                       1.0f, smem);
}

// Fused Q/K/V projection: one launch, grid (12, 32). blockIdx.x selects the
// target matrix (x>>2: 0=Q,1=K,2=V) and its 128-col tile (x&3).
// PLAIN bf16, compact smem (48KB). __launch_bounds__(256,2) so ptxas keeps
// 128 regs (the R16 (256,3) cap spilled and regressed).
// Q prescaled by 0.125*log2(e) so attention uses ex2 directly.
__global__ void __launch_bounds__(256, 2) gemm_qkv(
    const __nv_bfloat16* __restrict__ Ahi,
    const __nv_bfloat16* __restrict__ whi,
    const float* __restrict__ bq, const float* __restrict__ bk,
    const float* __restrict__ bv,
    __nv_bfloat16* __restrict__ q, __nv_bfloat16* __restrict__ k,
    __nv_bfloat16* __restrict__ v) {
    extern __shared__ char smem[];
    const int which = blockIdx.x >> 2;
    const int nx = blockIdx.x & 3;
    const __nv_bfloat16* Bhi = whi + (size_t)which * 262144;
    const float* bias = (which == 0) ? bq : (which == 1) ? bk : bv;
    __nv_bfloat16* Cq = (which == 0) ? q : (which == 1) ? k : v;
    const float oscale = (which == 0) ? 0.125f * 1.4426950408889634f : 1.0f;
    gemm_core<4, 1>(Ahi, nullptr, Bhi, nullptr, bias, nullptr, Cq, nullptr,
                    DMODEL, DMODEL, 0, DMODEL, blockIdx.y * 128, nx * 128,
                    oscale, smem);
}

// ---------------------------------------------------------------------------
// Flash attention with HMMA, plain bf16 (dilution-validated R13/R14).
// 128-q tiles, 256 threads, KV chunks of 64 keys, double-buffered cp.async.
// No online max; Q prescaled by 0.125*log2e -> bare ex2. Row-sum l via
// ones-mma on the packed P fragments.
// SMEM: stage s at s*16384: K 0 | V 8192.  Q at 32768.  Total 48KB.
// ---------------------------------------------------------------------------
#define ATT_SMEM 49152

__device__ __forceinline__ void att_stage_load(
    uint32_t sbase,
    const __nv_bfloat16* __restrict__ k, const __nv_bfloat16* __restrict__ v,
    size_t hoff, int key0, int tid) {
    #pragma unroll
    for (int t = 0; t < 2; t++) {
        int idx = tid + t * 256;
        int row = idx >> 3, c = idx & 7;
        uint32_t off = (uint32_t)row * 128 + (uint32_t)((c ^ (row & 7)) << 4);
        size_t g = hoff + (size_t)(key0 + row) * DMODEL + c * 8;
        CP_ASYNC16(sbase +        off, k + g);
        CP_ASYNC16(sbase + 8192 + off, v + g);
    }
}

__global__ void __launch_bounds__(256, 2) attn_hmma(
    const __nv_bfloat16* __restrict__ q,
    const __nv_bfloat16* __restrict__ k,
    const __nv_bfloat16* __restrict__ v,
    float* __restrict__ o) {
    extern __shared__ char smem[];
    const uint32_t su = smem_to_u32(smem);
    const int tid = threadIdx.x, lane = tid & 31, wid = tid >> 5;
    const int qt = blockIdx.x, hh = blockIdx.y, b = blockIdx.z;
    const size_t hoff = (size_t)b * SEQ * DMODEL + hh * 64;

    for (int i = tid; i < 1024; i += 256) {
        int row = i >> 3, c = i & 7;
        uint32_t off = (uint32_t)row * 128 + (uint32_t)((c ^ (row & 7)) << 4);
        size_t g = hoff + (size_t)(qt * 128 + row) * DMODEL + c * 8;
        *(uint4*)(smem + 32768 + off) = *(const uint4*)(q + g);
    }

    float O[8][4];
    #pragma unroll
    for (int j = 0; j < 8; j++)
        #pragma unroll
        for (int i = 0; i < 4; i++) O[j][i] = 0.f;
    float accl[4] = {0.f, 0.f, 0.f, 0.f};   // row-sum via ones-mma
    const uint32_t ones2[2] = {0x3F803F80u, 0x3F803F80u};  // bf16 1.0 x2

    __syncthreads();
    att_stage_load(su, k, v, hoff, 0, tid);
    CP_COMMIT();

    const int a_r = lane & 15;
    const int a_h = lane >> 4;
    const int b_r = (lane & 7) + ((lane >> 4) << 3);
    const int b_h = (lane >> 3) & 1;
    const int v_r = (lane & 7) + (((lane >> 3) & 1) << 3);
    const int v_h = lane >> 4;

    const int NCH = SEQ / 64;
    for (int ch = 0; ch < NCH; ch++) {
        if (ch + 1 < NCH) {
            att_stage_load(su + ((ch + 1) & 1) * 16384,
                           k, v, hoff, (ch + 1) * 64, tid);
            CP_COMMIT();
            CP_WAIT(1);
        } else {
            CP_WAIT(0);
        }
        __syncthreads();
        const uint32_t sb = su + (ch & 1) * 16384;

        float s[8][4];
        #pragma unroll
        for (int j = 0; j < 8; j++)
            #pragma unroll
            for (int i = 0; i < 4; i++) s[j][i] = 0.f;

        #pragma unroll
        for (int ks = 0; ks < 4; ks++) {
            uint32_t qf[4];
            {
                int row = wid * 16 + a_r;
                int c16 = ks * 2 + a_h;
                uint32_t off = (uint32_t)row * 128 +
                               (uint32_t)((c16 ^ (row & 7)) << 4);
                ldsm_x4(qf, su + 32768 + off);
            }
            #pragma unroll
            for (int j2 = 0; j2 < 4; j2++) {
                int row = j2 * 16 + b_r;
                int c16 = ks * 2 + b_h;
                uint32_t off = (uint32_t)row * 128 +
                               (uint32_t)((c16 ^ (row & 7)) << 4);
                uint32_t kb[4];
                ldsm_x4(kb, sb + off);
                mma_bf16(s[2*j2],   qf, kb);
                mma_bf16(s[2*j2+1], qf, kb + 2);
            }
        }

        // quirk + softmax numerator: p = 2^s (log2e pre-folded)
        #pragma unroll
        for (int j = 0; j < 8; j++) {
            #pragma unroll
            for (int i = 0; i < 4; i++) {
                float vv = s[j][i];
                if (vv == 0.f) vv = -1e9f;     // reference quirk
                s[j][i] = ex2f(vv);            // 2^(-1e9) underflows to 0
            }
        }

        // O += P V; l += P @ ones
        #pragma unroll
        for (int t = 0; t < 4; t++) {
            uint32_t pa[4];
            pa[0] = pack_bf16x2(s[2*t][0],   s[2*t][1]);
            pa[1] = pack_bf16x2(s[2*t][2],   s[2*t][3]);
            pa[2] = pack_bf16x2(s[2*t+1][0], s[2*t+1][1]);
            pa[3] = pack_bf16x2(s[2*t+1][2], s[2*t+1][3]);
            mma_bf16(accl, pa, ones2);
            #pragma unroll
            for (int n2 = 0; n2 < 4; n2++) {
                int row = t * 16 + v_r;
                int c16 = n2 * 2 + v_h;
                uint32_t off = (uint32_t)row * 128 +
                               (uint32_t)((c16 ^ (row & 7)) << 4);
                uint32_t vb[4];
                ldsm_x4_t(vb, sb + 8192 + off);
                mma_bf16(O[2*n2],   pa, vb);
                mma_bf16(O[2*n2+1], pa, vb + 2);
            }
        }
        __syncthreads();
    }

    float i0 = 1.f / accl[0], i1 = 1.f / accl[2];
    int r0 = qt * 128 + wid * 16 + (lane >> 2);
    int colb = hh * 64 + (lane & 3) * 2;
    #pragma unroll
    for (int j = 0; j < 8; j++) {
        int col = colb + j * 8;
        *(float2*)(o + ((size_t)b * SEQ + r0) * DMODEL + col) =
            make_float2(O[j][0] * i0, O[j][1] * i0);
        *(float2*)(o + ((size_t)b * SEQ + r0 + 8) * DMODEL + col) =
            make_float2(O[j][2] * i1, O[j][3] * i1);
    }
}

// ---------------------------------------------------------------------------
// Fused residual-add + LayerNorm, warp-per-row (no block syncs, no smem).
// 256 threads = 8 warps = 8 rows per CTA; each lane holds 16 columns
// (4 x float4 at stride 128). Emits fp32 + bf16 hi/lo.
// ---------------------------------------------------------------------------
__device__ __forceinline__ void ln_row(float x[16], int row, int lane,
                                       const float* __restrict__ g,
                                       const float* __restrict__ beta,
                                       float* __restrict__ out,
                                       __nv_bfloat16* __restrict__ ohi,
                                       __nv_bfloat16* __restrict__ olo) {
    float s = 0.f, s2 = 0.f;
    #pragma unroll
    for (int i = 0; i < 16; i++) { s += x[i]; s2 += x[i] * x[i]; }
    #pragma unroll
    for (int off = 16; off; off >>= 1) {
        s  += __shfl_xor_sync(0xffffffffu, s,  off);
        s2 += __shfl_xor_sync(0xffffffffu, s2, off);
    }
    float mean = s  * (1.f / (float)DMODEL);
    float var  = s2 * (1.f / (float)DMODEL) - mean * mean;
    float rstd = rsqrtf(var + 1e-5f);

    #pragma unroll
    for (int j = 0; j < 4; j++) {
        int col = lane * 4 + j * 128;
        float4 gg = *(const float4*)(g + col);
        float4 bb = *(const float4*)(beta + col);
        float y0 = (x[4*j+0] - mean) * rstd * gg.x + bb.x;
        float y1 = (x[4*j+1] - mean) * rstd * gg.y + bb.y;
        float y2 = (x[4*j+2] - mean) * rstd * gg.z + bb.z;
        float y3 = (x[4*j+3] - mean) * rstd * gg.w + bb.w;
        *(float4*)(out + (size_t)row * DMODEL + col) =
            make_float4(y0, y1, y2, y3);
        uint32_t h01, l01, h23, l23;
        split2(y0, y1, h01, l01);
        split2(y2, y3, h23, l23);
        uint2* ph = (uint2*)(ohi + (size_t)row * DMODEL + col);
        uint2* pl = (uint2*)(olo + (size_t)row * DMODEL + col);
        *ph = make_uint2(h01, h23);
        *pl = make_uint2(l01, l23);
    }
}

__global__ void __launch_bounds__(256) add_ln_kernel(
    const float* __restrict__ a, const float* __restrict__ r,
    const float* __restrict__ g, const float* __restrict__ beta,
    float* __restrict__ out,
    __nv_bfloat16* __restrict__ ohi, __nv_bfloat16* __restrict__ olo) {
    const int row = blockIdx.x * 8 + (threadIdx.x >> 5);
    const int lane = threadIdx.x & 31;
    float x[16];
    #pragma unroll
    for (int j = 0; j < 4; j++) {
        int col = lane * 4 + j * 128;
        float4 va = *(const float4*)(a + (size_t)row * DMODEL + col);
        float4 vr = *(const float4*)(r + (size_t)row * DMODEL + col);
        x[4*j+0] = va.x + vr.x;
        x[4*j+1] = va.y + vr.y;
        x[4*j+2] = va.z + vr.z;
        x[4*j+3] = va.w + vr.w;
    }
    ln_row(x, row, lane, g, beta, out, ohi, olo);
}

__global__ void __launch_bounds__(256) add_ln3_kernel(
    const float* __restrict__ a0, const float* __restrict__ a1,
    const float* __restrict__ b2, const float* __restrict__ r,
    const float* __restrict__ g, const float* __restrict__ beta,
    float* __restrict__ out,
    __nv_bfloat16* __restrict__ ohi, __nv_bfloat16* __restrict__ olo) {
    const int row = blockIdx.x * 8 + (threadIdx.x >> 5);
    const int lane = threadIdx.x & 31;
    float x[16];
    #pragma unroll
    for (int j = 0; j < 4; j++) {
        int col = lane * 4 + j * 128;
        float4 v0 = *(const float4*)(a0 + (size_t)row * DMODEL + col);
        float4 v1 = *(const float4*)(a1 + (size_t)row * DMODEL + col);
        float4 vb = *(const float4*)(b2 + col);
        float4 vr = *(const float4*)(r + (size_t)row * DMODEL + col);
        x[4*j+0] = v0.x + v1.x + vb.x + vr.x;
        x[4*j+1] = v0.y + v1.y + vb.y + vr.y;
        x[4*j+2] = v0.z + v1.z + vb.z + vr.z;
        x[4*j+3] = v0.w + v1.w + vb.w + vr.w;
    }
    ln_row(x, row, lane, g, beta, out, ohi, olo);
}

// ---------------------------------------------------------------------------
// Launch
// ---------------------------------------------------------------------------
extern "C" void kernel_launch(void* const* d_in, const int* in_sizes, int n_in,
                              void* d_out, int out_size) {
    const float* x   = (const float*)d_in[0];
    const float* Wq  = (const float*)d_in[1];
    const float* bq  = (const float*)d_in[2];
    const float* Wk  = (const float*)d_in[3];
    const float* bk  = (const float*)d_in[4];
    const float* Wv  = (const float*)d_in[5];
    const float* bv  = (const float*)d_in[6];
    const float* W1  = (const float*)d_in[7];
    const float* b1  = (const float*)d_in[8];
    const float* W2  = (const float*)d_in[9];
    const float* b2  = (const float*)d_in[10];
    const float* g1  = (const float*)d_in[11];
    const float* be1 = (const float*)d_in[12];
    const float* g2  = (const float*)d_in[13];
    const float* be2 = (const float*)d_in[14];
    float* out = (float*)d_out;

    float *h_, *at_, *h1_, *f2_;
    cudaGetSymbolAddress((void**)&h_,  g_h);
    cudaGetSymbolAddress((void**)&at_, g_at);
    cudaGetSymbolAddress((void**)&h1_, g_h1);
    cudaGetSymbolAddress((void**)&f2_, g_f2);
    __nv_bfloat16 *whi, *wlo;
    cudaGetSymbolAddress((void**)&whi, g_w_hi);
    cudaGetSymbolAddress((void**)&wlo, g_w_lo);
    __nv_bfloat16 *hh, *hl, *q_, *k_, *v_, *h1h, *h1l, *ffh, *ffl;
    cudaGetSymbolAddress((void**)&hh,  g_hh);
    cudaGetSymbolAddress((void**)&hl,  g_hl);
    cudaGetSymbolAddress((void**)&q_,  g_q);
    cudaGetSymbolAddress((void**)&k_,  g_k);
    cudaGetSymbolAddress((void**)&v_,  g_v);
    cudaGetSymbolAddress((void**)&h1h, g_h1h);
    cudaGetSymbolAddress((void**)&h1l, g_h1l);
    cudaGetSymbolAddress((void**)&ffh, g_ffh);
    cudaGetSymbolAddress((void**)&ffl, g_ffl);

    cudaFuncSetAttribute(gemm_hmma<2>,
                         cudaFuncAttributeMaxDynamicSharedMemorySize, GEMM_SMEM);
    cudaFuncSetAttribute(gemm_hmma<3>,
                         cudaFuncAttributeMaxDynamicSharedMemorySize, GEMM_SMEM);
    cudaFuncSetAttribute(gemm_qkv,
                         cudaFuncAttributeMaxDynamicSharedMemorySize, QKV_SMEM);
    cudaFuncSetAttribute(attn_hmma,
                         cudaFuncAttributeMaxDynamicSharedMemorySize, ATT_SMEM);

    const int M = MROWS;
    dim3 thr256(256);

    // Pre-split + transpose all weights (single launch).
    wsplit_all<<<NBLK * 2816, dim3(32, 8)>>>(Wq, Wk, Wv, W1, W2, whi, wlo);

    dim3 g_qkv(12, M/128);               // fused QKV: 384 CTAs
    dim3 g_ff1(DFF/128,    M/128);       // (16, 32) = 512 CTAs
    dim3 g_ff2(DMODEL/128, M/128, 2);    // split-K=2: 256 CTAs
    dim3 g_att(SEQ/128, NHEAD, BATCH);   // (16, 8, 2) = 256 CTAs
    const int g_ln = M / 8;              // warp-per-row LN: 512 CTAs

    // Layer-0 input split.
    split_kernel<<<(M*DMODEL/4 + 255)/256, thr256>>>(x, hh, hl, M*DMODEL/4);

    for (int l = 0; l < NBLK; l++) {
        const float* hin = (l == 0) ? x : h_;
        size_t wb = (size_t)l * WSTRIDE;

        gemm_qkv<<<g_qkv, thr256, QKV_SMEM>>>(
            hh, whi + wb,
            bq + (size_t)l*DMODEL, bk + (size_t)l*DMODEL, bv + (size_t)l*DMODEL,
            q_, k_, v_);

        attn_hmma<<<g_att, thr256, ATT_SMEM>>>(q_, k_, v_, at_);

        add_ln_kernel<<<g_ln, thr256>>>(at_, hin, g1 + (size_t)l*DMODEL,
                                        be1 + (size_t)l*DMODEL, h1_, h1h, h1l);

        gemm_hmma<2><<<g_ff1, thr256, GEMM_SMEM>>>(
            h1h, h1l, whi + wb + WOFF_1, wlo + wb + WOFF_1,
            b1 + (size_t)l*DFF, nullptr, ffh, ffl, DFF, DMODEL, DMODEL);

        gemm_hmma<3><<<g_ff2, thr256, GEMM_SMEM>>>(
            ffh, ffl, whi + wb + WOFF_2, wlo + wb + WOFF_2,
            nullptr, f2_, nullptr, nullptr, DMODEL, DFF, DFF/2);

        float* hout = (l == NBLK - 1) ? out : h_;
        add_ln3_kernel<<<g_ln, thr256>>>(f2_, f2_ + (size_t)M*DMODEL,
                                         b2 + (size_t)l*DMODEL, h1_,
                                         g2 + (size_t)l*DMODEL,
                                         be2 + (size_t)l*DMODEL, hout, hh, hl);
    }
}